// round 10
// baseline (speedup 1.0000x reference)
#include <cuda_runtime.h>
#include <cuda_bf16.h>
#include <cstdint>

#define Bx 1024
#define Tx 512
#define Kx 64
#define WPB 7
#define GRID ((Bx + WPB - 1) / WPB)   // 147

// v rows: g_v[(b*511 + t)*32 + l] = (v_t[l], v_t[l+32]), t = 0..510
// M rows: g_m[(b*511 + (t-1))*32 + l] = (M_t[l], M_t[l+32]), t = 1..511
//         where M_t[j] = max_i(v_{t-1}[i] + T[i][j])  (pre-emission max)
__device__ float2 g_v[(long)Bx * 511 * 32];
__device__ float2 g_m[(long)Bx * 511 * 32];
__device__ int g_last[Bx];

#define NEG_INF __int_as_float(0xff800000)

__global__ __launch_bounds__(WPB * 32, 1) void crf_forward(
    const float* __restrict__ em, const int* __restrict__ mask,
    const float* __restrict__ trans, const float* __restrict__ startt,
    const float* __restrict__ endt, float* __restrict__ out)
{
    // smem: i in [32,64) only (i in [0,32) lives in registers)
    __shared__ float2 Tsm[32 * 32];          // Tsm[(i-32)*32+l] = (T[i][l], T[i][l+32])
    __shared__ unsigned int Esm[32 * 32];    // bf16x2(exp(T[i][l]), exp(T[i][l+32]))
    __shared__ __align__(16) float2 AV[WPB][Kx];   // (s_i, v_i)
    __shared__ unsigned char maskb[WPB][Tx];

    const int tid = threadIdx.x;
    const int w = tid >> 5;
    const int l = tid & 31;
    const int b = blockIdx.x * WPB + w;
    const bool active = (b < Bx);

    for (int idx = tid; idx < 32 * 32; idx += WPB * 32) {
        int i = (idx >> 5) + 32, c = idx & 31;
        float t0 = trans[i * Kx + c];
        float t1 = trans[i * Kx + c + 32];
        Tsm[idx] = make_float2(t0, t1);
        __nv_bfloat162 h = __float22bfloat162_rn(make_float2(__expf(t0), __expf(t1)));
        Esm[idx] = *reinterpret_cast<unsigned int*>(&h);
    }
    if (active) {
        for (int t = l; t < Tx; t += 32)
            maskb[w][t] = (unsigned char)(mask[b * Tx + t] != 0);
    }
    __syncthreads();
    if (!active) return;

    // registers: i in [0,32)  (96 array regs total — proven to colour cleanly)
    float tr0[32], tr1[32];
    unsigned int ee[32];
    #pragma unroll
    for (int i = 0; i < 32; ++i) {
        tr0[i] = trans[i * Kx + l];
        tr1[i] = trans[i * Kx + l + 32];
        __nv_bfloat162 h = __float22bfloat162_rn(
            make_float2(__expf(tr0[i]), __expf(tr1[i])));
        ee[i] = *reinterpret_cast<unsigned int*>(&h);
    }

    const float* emp = em + (long)b * Tx * Kx;
    float2* vout = g_v + (long)b * 511 * 32 + l;
    float2* mout = g_m + (long)b * 511 * 32 + l;

    const float a0i = startt[l] + emp[l];
    const float a1i = startt[l + 32] + emp[l + 32];
    float v0 = a0i, v1 = a1i;
    // linear-domain forward state: alpha_j = L + log(s_j)
    float s0 = __expf(a0i);
    float s1 = __expf(a1i);
    float L = 0.f;

    vout[0] = make_float2(v0, v1);   // row t=0

    for (int t = 1; t < Tx; ++t) {
        const float e0 = __ldg(emp + t * Kx + l);
        const float e1 = __ldg(emp + t * Kx + l + 32);
        const float eem0 = __expf(e0);     // off the serial chain
        const float eem1 = __expf(e1);
        const int mt = maskb[w][t];

        AV[w][l]      = make_float2(s0, v0);
        AV[w][l + 32] = make_float2(s1, v1);
        __syncwarp();

        // two independent chains (A: even offset, B: odd) per output for ILP
        float acc0A = 0.f, acc0B = 0.f, acc1A = 0.f, acc1B = 0.f;
        float b0A = NEG_INF, b0B = NEG_INF, b1A = NEG_INF, b1B = NEG_INF;

        // ---- i in [0,32): register-resident T/E ----
        #pragma unroll
        for (int ii = 0; ii < 16; ++ii) {
            const int i = 2 * ii;
            const float4 q = *(const float4*)(&AV[w][i]);   // s_i,v_i,s_{i+1},v_{i+1}
            {
                unsigned int ep = ee[i];
                float ef0 = __uint_as_float(ep << 16);
                float ef1 = __uint_as_float(ep & 0xffff0000u);
                acc0A += q.x * ef0;  acc1A += q.x * ef1;
                b0A = fmaxf(b0A, q.y + tr0[i]);
                b1A = fmaxf(b1A, q.y + tr1[i]);
            }
            {
                unsigned int ep = ee[i + 1];
                float ef0 = __uint_as_float(ep << 16);
                float ef1 = __uint_as_float(ep & 0xffff0000u);
                acc0B += q.z * ef0;  acc1B += q.z * ef1;
                b0B = fmaxf(b0B, q.w + tr0[i + 1]);
                b1B = fmaxf(b1B, q.w + tr1[i + 1]);
            }
        }
        // ---- i in [32,64): smem-resident T/E ----
        #pragma unroll
        for (int ii = 0; ii < 16; ++ii) {
            const int is = 2 * ii;               // smem-local i
            const float4 q = *(const float4*)(&AV[w][32 + is]);
            {
                float2 tp = Tsm[is * 32 + l];
                unsigned int ep = Esm[is * 32 + l];
                float ef0 = __uint_as_float(ep << 16);
                float ef1 = __uint_as_float(ep & 0xffff0000u);
                acc0A += q.x * ef0;  acc1A += q.x * ef1;
                b0A = fmaxf(b0A, q.y + tp.x);
                b1A = fmaxf(b1A, q.y + tp.y);
            }
            {
                float2 tp = Tsm[(is + 1) * 32 + l];
                unsigned int ep = Esm[(is + 1) * 32 + l];
                float ef0 = __uint_as_float(ep << 16);
                float ef1 = __uint_as_float(ep & 0xffff0000u);
                acc0B += q.z * ef0;  acc1B += q.z * ef1;
                b0B = fmaxf(b0B, q.w + tp.x);
                b1B = fmaxf(b1B, q.w + tp.y);
            }
        }

        const float M0 = fmaxf(b0A, b0B);     // pre-emission max (exact)
        const float M1 = fmaxf(b1A, b1B);
        const float ns0 = (acc0A + acc0B) * eem0;
        const float ns1 = (acc1A + acc1B) * eem1;
        const float nv0 = M0 + e0;
        const float nv1 = M1 + e1;

        mout[(t - 1) * 32] = make_float2(M0, M1);   // off-chain store

        if (mt) { s0 = ns0; s1 = ns1; v0 = nv0; v1 = nv1; }

        if (t < 511) vout[t * 32] = make_float2(v0, v1);

        // periodic renormalization (scale-invariant; L tracks the log)
        if ((t & 3) == 0) {
            float c = __shfl_sync(0xffffffffu, s0, 0);
            float r = __fdividef(1.0f, c);
            s0 *= r; s1 *= r;
            L += __logf(c);
        }
    }

    // ---- logZ = logsumexp(alpha + end),  alpha_j = L + log(s_j) ----
    const float x0 = L + __logf(s0) + endt[l];
    const float x1 = L + __logf(s1) + endt[l + 32];
    float mm = fmaxf(x0, x1);
    #pragma unroll
    for (int o = 16; o; o >>= 1)
        mm = fmaxf(mm, __shfl_xor_sync(0xffffffffu, mm, o));
    float s = __expf(x0 - mm) + __expf(x1 - mm);
    #pragma unroll
    for (int o = 16; o; o >>= 1)
        s += __shfl_xor_sync(0xffffffffu, s, o);
    const float logZ = mm + __logf(s);

    // ---- last tag: argmax(v + end), first-index tie-break ----
    AV[w][l].x      = v0 + endt[l];
    AV[w][l + 32].x = v1 + endt[l + 32];
    __syncwarp();
    if (l == 0) {
        float bb = AV[w][0].x; int aa = 0;
        for (int i = 1; i < Kx; ++i) {
            float x = AV[w][i].x;
            if (x > bb) { bb = x; aa = i; }
        }
        g_last[b] = aa;
        out[b] = logZ;
    }
}

#define BTW 8   // warps per backtrace block; each warp handles 2 batches

__global__ __launch_bounds__(BTW * 32) void crf_backtrace(
    const float* __restrict__ em, const int* __restrict__ tags,
    const int* __restrict__ mask, const float* __restrict__ trans,
    const float* __restrict__ startt, const float* __restrict__ endt,
    float* __restrict__ out)
{
    // Tt[c][l] = (T[l][c], T[l+32][c])  — transposed, paired
    __shared__ float2 Tt[Kx][32];
    __shared__ unsigned char path_s[2 * BTW][Tx];
    __shared__ unsigned char mk[2 * BTW][Tx];

    const int tid = threadIdx.x;
    const int w = tid >> 5;
    const int l = tid & 31;
    const int bA = blockIdx.x * (2 * BTW) + 2 * w;
    const int bB = bA + 1;
    const int sA = 2 * w, sB = 2 * w + 1;

    for (int idx = tid; idx < Kx * 32; idx += BTW * 32) {
        int c = idx >> 5, r = idx & 31;
        Tt[c][r] = make_float2(trans[r * Kx + c], trans[(r + 32) * Kx + c]);
    }
    for (int t = l; t < Tx; t += 32) {
        mk[sA][t] = (unsigned char)(mask[bA * Tx + t] != 0);
        mk[sB][t] = (unsigned char)(mask[bB * Tx + t] != 0);
    }
    __syncthreads();

    // ---- gold score for both batches (warp-parallel) ----
    #pragma unroll
    for (int p = 0; p < 2; ++p) {
        const int b = (p == 0) ? bA : bB;
        const int sl = (p == 0) ? sA : sB;
        float gp = 0.f; int cnt = 0;
        for (int t = l; t < Tx; t += 32) {
            int mkt = mk[sl][t];
            float mf = (float)mkt;
            cnt += mkt;
            int tg = tags[b * Tx + t];
            gp += em[((long)b * Tx + t) * Kx + tg] * mf;
            if (t > 0)
                gp += trans[tags[b * Tx + t - 1] * Kx + tg] * mf;
        }
        #pragma unroll
        for (int o = 16; o; o >>= 1) {
            gp  += __shfl_xor_sync(0xffffffffu, gp, o);
            cnt += __shfl_xor_sync(0xffffffffu, cnt, o);
        }
        if (l == 0) {
            int tg0 = tags[b * Tx];
            int tgl = tags[b * Tx + cnt - 1];
            out[b] = out[b] - (gp + startt[tg0] + endt[tgl]);  // nll
        }
    }

    // ---- dual-chain path recovery: equality search against stored M ----
    // step s = 0..510 -> t = 511-s; consumes v row (t-1) and M row (t-1),
    // both at ring index 510-s.
    const float2* vrA = g_v + (long)bA * 511 * 32 + l;
    const float2* vrB = g_v + (long)bB * 511 * 32 + l;
    const float2* mrA = g_m + (long)bA * 511 * 32 + l;
    const float2* mrB = g_m + (long)bB * 511 * 32 + l;
    int curA = g_last[bA];
    int curB = g_last[bB];
    path_s[sA][Tx - 1] = (unsigned char)curA;
    path_s[sB][Tx - 1] = (unsigned char)curB;

    float2 ringVA[8], ringVB[8], ringMA[8], ringMB[8];
    #pragma unroll
    for (int k = 0; k < 8; ++k) {
        ringVA[k] = __ldg(vrA + (510 - k) * 32);
        ringVB[k] = __ldg(vrB + (510 - k) * 32);
        ringMA[k] = __ldg(mrA + (510 - k) * 32);
        ringMB[k] = __ldg(mrB + (510 - k) * 32);
    }

    #define BT_STEP2(S, VA, VB, MA, MB)                                      \
    {                                                                        \
        const int t_ = 511 - (S);                                            \
        float2 tpA = Tt[curA][l];                                            \
        float2 tpB = Tt[curB][l];                                            \
        float mcA = __shfl_sync(0xffffffffu,                                 \
                                (curA < 32) ? (MA).x : (MA).y, curA & 31);   \
        float mcB = __shfl_sync(0xffffffffu,                                 \
                                (curB < 32) ? (MB).x : (MB).y, curB & 31);   \
        unsigned int mA0 = __ballot_sync(0xffffffffu, (VA).x + tpA.x == mcA);\
        unsigned int mA1 = __ballot_sync(0xffffffffu, (VA).y + tpA.y == mcA);\
        unsigned int mB0 = __ballot_sync(0xffffffffu, (VB).x + tpB.x == mcB);\
        unsigned int mB1 = __ballot_sync(0xffffffffu, (VB).y + tpB.y == mcB);\
        int ncA = mA0 ? (__ffs(mA0) - 1) : (32 + __ffs(mA1) - 1);            \
        int ncB = mB0 ? (__ffs(mB0) - 1) : (32 + __ffs(mB1) - 1);            \
        curA = mk[sA][t_] ? ncA : curA;                                      \
        curB = mk[sB][t_] ? ncB : curB;                                      \
        path_s[sA][t_ - 1] = (unsigned char)curA;                            \
        path_s[sB][t_ - 1] = (unsigned char)curB;                            \
    }

    for (int s0 = 0; s0 < 504; s0 += 8) {
        #pragma unroll
        for (int k = 0; k < 8; ++k) {
            const int s = s0 + k;
            const float2 vA = ringVA[k];
            const float2 vB = ringVB[k];
            const float2 mA = ringMA[k];
            const float2 mB = ringMB[k];
            const int rp = 510 - (s + 8);           // row for step s+8
            const int rpc = (rp >= 0 ? rp : 0) * 32;
            ringVA[k] = __ldg(vrA + rpc);
            ringVB[k] = __ldg(vrB + rpc);
            ringMA[k] = __ldg(mrA + rpc);
            ringMB[k] = __ldg(mrB + rpc);
            BT_STEP2(s, vA, vB, mA, mB);
        }
    }
    #pragma unroll
    for (int k = 0; k < 7; ++k) {
        const int s = 504 + k;
        const float2 vA = ringVA[k];
        const float2 vB = ringVB[k];
        const float2 mA = ringMA[k];
        const float2 mB = ringMB[k];
        BT_STEP2(s, vA, vB, mA, mB);
    }
    #undef BT_STEP2

    __syncwarp();
    for (int t = l; t < Tx; t += 32) {
        out[Bx + (long)bA * Tx + t] = (float)path_s[sA][t];
        out[Bx + (long)bB * Tx + t] = (float)path_s[sB][t];
    }
}

extern "C" void kernel_launch(void* const* d_in, const int* in_sizes, int n_in,
                              void* d_out, int out_size)
{
    const float* em     = (const float*)d_in[0];
    const int*   tags   = (const int*)d_in[1];
    const int*   mask   = (const int*)d_in[2];
    const float* trans  = (const float*)d_in[3];
    const float* startt = (const float*)d_in[4];
    const float* endt   = (const float*)d_in[5];
    float* out = (float*)d_out;

    crf_forward<<<GRID, WPB * 32>>>(em, mask, trans, startt, endt, out);
    crf_backtrace<<<Bx / (2 * BTW), BTW * 32>>>(em, tags, mask, trans, startt, endt, out);
}

// round 11
// speedup vs baseline: 1.4415x; 1.4415x over previous
#include <cuda_runtime.h>
#include <cuda_bf16.h>
#include <cstdint>

#define Bx 1024
#define Tx 512
#define Kx 64
#define WPB 7
#define GRID ((Bx + WPB - 1) / WPB)   // 147

// v rows: g_v[(b*511 + t)*32 + l] = (v_t[l], v_t[l+32]), t = 0..510
__device__ float2 g_v[(long)Bx * 511 * 32];
__device__ int g_last[Bx];

#define NEG_INF __int_as_float(0xff800000)

__global__ __launch_bounds__(WPB * 32, 1) void crf_forward(
    const float* __restrict__ em, const int* __restrict__ mask,
    const float* __restrict__ trans, const float* __restrict__ startt,
    const float* __restrict__ endt, float* __restrict__ out)
{
    // smem: i in [32,64) fused: TEsm[(i-32)*32+l] = (T[i][l], T[i][l+32],
    //       bits(bf16x2(E[i][l],E[i][l+32])), unused) — one LDS.128 per (i,l)
    __shared__ __align__(16) float4 TEsm[32 * 32];
    __shared__ __align__(16) float2 AV[WPB][Kx];   // (s_i, v_i)
    __shared__ unsigned char maskb[WPB][Tx];

    const int tid = threadIdx.x;
    const int w = tid >> 5;
    const int l = tid & 31;
    const int b = blockIdx.x * WPB + w;
    const bool active = (b < Bx);

    for (int idx = tid; idx < 32 * 32; idx += WPB * 32) {
        int i = (idx >> 5) + 32, c = idx & 31;
        float t0 = trans[i * Kx + c];
        float t1 = trans[i * Kx + c + 32];
        __nv_bfloat162 h = __float22bfloat162_rn(make_float2(__expf(t0), __expf(t1)));
        TEsm[idx] = make_float4(t0, t1,
                                __uint_as_float(*reinterpret_cast<unsigned int*>(&h)),
                                0.f);
    }
    if (active) {
        for (int t = l; t < Tx; t += 32)
            maskb[w][t] = (unsigned char)(mask[b * Tx + t] != 0);
    }
    __syncthreads();
    if (!active) return;

    // registers: i in [0,32)  (96 array regs total — proven to colour cleanly)
    float tr0[32], tr1[32];
    unsigned int ee[32];
    #pragma unroll
    for (int i = 0; i < 32; ++i) {
        tr0[i] = trans[i * Kx + l];
        tr1[i] = trans[i * Kx + l + 32];
        __nv_bfloat162 h = __float22bfloat162_rn(
            make_float2(__expf(tr0[i]), __expf(tr1[i])));
        ee[i] = *reinterpret_cast<unsigned int*>(&h);
    }

    const float* emp = em + (long)b * Tx * Kx;
    float2* vout = g_v + (long)b * 511 * 32 + l;

    const float a0i = startt[l] + emp[l];
    const float a1i = startt[l + 32] + emp[l + 32];
    float v0 = a0i, v1 = a1i;
    // linear-domain forward state: alpha_j = L + log(s_j)
    float s0 = __expf(a0i);
    float s1 = __expf(a1i);
    float L = 0.f;

    __stcs(&vout[0], make_float2(v0, v1));   // row t=0

    for (int t = 1; t < Tx; ++t) {
        const float e0 = __ldg(emp + t * Kx + l);
        const float e1 = __ldg(emp + t * Kx + l + 32);
        const float eem0 = __expf(e0);     // off the serial chain
        const float eem1 = __expf(e1);
        const int mt = maskb[w][t];

        AV[w][l]      = make_float2(s0, v0);
        AV[w][l + 32] = make_float2(s1, v1);
        __syncwarp();

        // two independent chains (A: even offset, B: odd) per output for ILP
        float acc0A = 0.f, acc0B = 0.f, acc1A = 0.f, acc1B = 0.f;
        float b0A = NEG_INF, b0B = NEG_INF, b1A = NEG_INF, b1B = NEG_INF;

        // ---- i in [0,32): register-resident T/E ----
        #pragma unroll
        for (int ii = 0; ii < 16; ++ii) {
            const int i = 2 * ii;
            const float4 q = *(const float4*)(&AV[w][i]);   // s_i,v_i,s_{i+1},v_{i+1}
            {
                unsigned int ep = ee[i];
                float ef0 = __uint_as_float(ep << 16);
                float ef1 = __uint_as_float(ep & 0xffff0000u);
                acc0A += q.x * ef0;  acc1A += q.x * ef1;
                b0A = fmaxf(b0A, q.y + tr0[i]);
                b1A = fmaxf(b1A, q.y + tr1[i]);
            }
            {
                unsigned int ep = ee[i + 1];
                float ef0 = __uint_as_float(ep << 16);
                float ef1 = __uint_as_float(ep & 0xffff0000u);
                acc0B += q.z * ef0;  acc1B += q.z * ef1;
                b0B = fmaxf(b0B, q.w + tr0[i + 1]);
                b1B = fmaxf(b1B, q.w + tr1[i + 1]);
            }
        }
        // ---- i in [32,64): smem-resident fused T/E (one LDS.128 each) ----
        #pragma unroll
        for (int ii = 0; ii < 16; ++ii) {
            const int is = 2 * ii;               // smem-local i
            const float4 q = *(const float4*)(&AV[w][32 + is]);
            {
                float4 te = TEsm[is * 32 + l];
                unsigned int ep = __float_as_uint(te.z);
                float ef0 = __uint_as_float(ep << 16);
                float ef1 = __uint_as_float(ep & 0xffff0000u);
                acc0A += q.x * ef0;  acc1A += q.x * ef1;
                b0A = fmaxf(b0A, q.y + te.x);
                b1A = fmaxf(b1A, q.y + te.y);
            }
            {
                float4 te = TEsm[(is + 1) * 32 + l];
                unsigned int ep = __float_as_uint(te.z);
                float ef0 = __uint_as_float(ep << 16);
                float ef1 = __uint_as_float(ep & 0xffff0000u);
                acc0B += q.z * ef0;  acc1B += q.z * ef1;
                b0B = fmaxf(b0B, q.w + te.x);
                b1B = fmaxf(b1B, q.w + te.y);
            }
        }

        const float ns0 = (acc0A + acc0B) * eem0;
        const float ns1 = (acc1A + acc1B) * eem1;
        const float nv0 = fmaxf(b0A, b0B) + e0;
        const float nv1 = fmaxf(b1A, b1B) + e1;

        if (mt) { s0 = ns0; s1 = ns1; v0 = nv0; v1 = nv1; }

        if (t < 511) __stcs(&vout[t * 32], make_float2(v0, v1));

        // periodic renormalization (scale-invariant; L tracks the log)
        if ((t & 3) == 0) {
            float c = __shfl_sync(0xffffffffu, s0, 0);
            float r = __fdividef(1.0f, c);
            s0 *= r; s1 *= r;
            L += __logf(c);
        }
    }

    // ---- logZ = logsumexp(alpha + end),  alpha_j = L + log(s_j) ----
    const float x0 = L + __logf(s0) + endt[l];
    const float x1 = L + __logf(s1) + endt[l + 32];
    float mm = fmaxf(x0, x1);
    #pragma unroll
    for (int o = 16; o; o >>= 1)
        mm = fmaxf(mm, __shfl_xor_sync(0xffffffffu, mm, o));
    float s = __expf(x0 - mm) + __expf(x1 - mm);
    #pragma unroll
    for (int o = 16; o; o >>= 1)
        s += __shfl_xor_sync(0xffffffffu, s, o);
    const float logZ = mm + __logf(s);

    // ---- last tag: argmax(v + end), first-index tie-break ----
    AV[w][l].x      = v0 + endt[l];
    AV[w][l + 32].x = v1 + endt[l + 32];
    __syncwarp();
    if (l == 0) {
        float bb = AV[w][0].x; int aa = 0;
        for (int i = 1; i < Kx; ++i) {
            float x = AV[w][i].x;
            if (x > bb) { bb = x; aa = i; }
        }
        g_last[b] = aa;
        out[b] = logZ;
    }
}

// Monotone bijective float -> u32 key (total order identical to < on finite floats)
__device__ __forceinline__ unsigned int fkey(float f) {
    unsigned int u = __float_as_uint(f);
    return (u & 0x80000000u) ? ~u : (u | 0x80000000u);
}

#define BTW 8   // warps per backtrace block; each warp handles 2 batches

__global__ __launch_bounds__(BTW * 32) void crf_backtrace(
    const float* __restrict__ em, const int* __restrict__ tags,
    const int* __restrict__ mask, const float* __restrict__ trans,
    const float* __restrict__ startt, const float* __restrict__ endt,
    float* __restrict__ out)
{
    // Tt[c][l] = (T[l][c], T[l+32][c])  — transposed, paired
    __shared__ float2 Tt[Kx][32];
    __shared__ unsigned char path_s[2 * BTW][Tx];
    __shared__ unsigned char mk[2 * BTW][Tx];

    const int tid = threadIdx.x;
    const int w = tid >> 5;
    const int l = tid & 31;
    const int bA = blockIdx.x * (2 * BTW) + 2 * w;
    const int bB = bA + 1;
    const int sA = 2 * w, sB = 2 * w + 1;

    for (int idx = tid; idx < Kx * 32; idx += BTW * 32) {
        int c = idx >> 5, r = idx & 31;
        Tt[c][r] = make_float2(trans[r * Kx + c], trans[(r + 32) * Kx + c]);
    }
    for (int t = l; t < Tx; t += 32) {
        mk[sA][t] = (unsigned char)(mask[bA * Tx + t] != 0);
        mk[sB][t] = (unsigned char)(mask[bB * Tx + t] != 0);
    }
    __syncthreads();

    // ---- gold score for both batches (warp-parallel) ----
    #pragma unroll
    for (int p = 0; p < 2; ++p) {
        const int b = (p == 0) ? bA : bB;
        const int sl = (p == 0) ? sA : sB;
        float gp = 0.f; int cnt = 0;
        for (int t = l; t < Tx; t += 32) {
            int mkt = mk[sl][t];
            float mf = (float)mkt;
            cnt += mkt;
            int tg = tags[b * Tx + t];
            gp += em[((long)b * Tx + t) * Kx + tg] * mf;
            if (t > 0)
                gp += trans[tags[b * Tx + t - 1] * Kx + tg] * mf;
        }
        #pragma unroll
        for (int o = 16; o; o >>= 1) {
            gp  += __shfl_xor_sync(0xffffffffu, gp, o);
            cnt += __shfl_xor_sync(0xffffffffu, cnt, o);
        }
        if (l == 0) {
            int tg0 = tags[b * Tx];
            int tgl = tags[b * Tx + cnt - 1];
            out[b] = out[b] - (gp + startt[tg0] + endt[tgl]);  // nll
        }
    }

    // ---- dual-chain path recovery: two independent batches interleaved ----
    const float2* vrA = g_v + (long)bA * 511 * 32 + l;
    const float2* vrB = g_v + (long)bB * 511 * 32 + l;
    int curA = g_last[bA];
    int curB = g_last[bB];
    path_s[sA][Tx - 1] = (unsigned char)curA;
    path_s[sB][Tx - 1] = (unsigned char)curB;

    float2 ringA[8], ringB[8];
    #pragma unroll
    for (int k = 0; k < 8; ++k) {
        ringA[k] = __ldg(vrA + (510 - k) * 32);
        ringB[k] = __ldg(vrB + (510 - k) * 32);
    }

    #define BT_STEP2(S, VA, VB)                                              \
    {                                                                        \
        const int t_ = 511 - (S);                                            \
        float2 tpA = Tt[curA][l];                                            \
        float2 tpB = Tt[curB][l];                                            \
        unsigned int kA0 = fkey((VA).x + tpA.x);                             \
        unsigned int kA1 = fkey((VA).y + tpA.y);                             \
        unsigned int kB0 = fkey((VB).x + tpB.x);                             \
        unsigned int kB1 = fkey((VB).y + tpB.y);                             \
        unsigned int kmA = __reduce_max_sync(0xffffffffu,                    \
                                             kA0 > kA1 ? kA0 : kA1);         \
        unsigned int kmB = __reduce_max_sync(0xffffffffu,                    \
                                             kB0 > kB1 ? kB0 : kB1);         \
        unsigned int mA0 = __ballot_sync(0xffffffffu, kA0 == kmA);           \
        unsigned int mA1 = __ballot_sync(0xffffffffu, kA1 == kmA);           \
        unsigned int mB0 = __ballot_sync(0xffffffffu, kB0 == kmB);           \
        unsigned int mB1 = __ballot_sync(0xffffffffu, kB1 == kmB);           \
        int ncA = mA0 ? (__ffs(mA0) - 1) : (32 + __ffs(mA1) - 1);            \
        int ncB = mB0 ? (__ffs(mB0) - 1) : (32 + __ffs(mB1) - 1);            \
        curA = mk[sA][t_] ? ncA : curA;                                      \
        curB = mk[sB][t_] ? ncB : curB;                                      \
        path_s[sA][t_ - 1] = (unsigned char)curA;                            \
        path_s[sB][t_ - 1] = (unsigned char)curB;                            \
    }

    for (int s0 = 0; s0 < 504; s0 += 8) {
        #pragma unroll
        for (int k = 0; k < 8; ++k) {
            const int s = s0 + k;
            const float2 vA = ringA[k];
            const float2 vB = ringB[k];
            const int rp = 510 - (s + 8);           // row for step s+8
            const int rpc = (rp >= 0 ? rp : 0) * 32;
            ringA[k] = __ldg(vrA + rpc);
            ringB[k] = __ldg(vrB + rpc);
            BT_STEP2(s, vA, vB);
        }
    }
    #pragma unroll
    for (int k = 0; k < 7; ++k) {
        const int s = 504 + k;
        const float2 vA = ringA[k];
        const float2 vB = ringB[k];
        BT_STEP2(s, vA, vB);
    }
    #undef BT_STEP2

    __syncwarp();
    for (int t = l; t < Tx; t += 32) {
        out[Bx + (long)bA * Tx + t] = (float)path_s[sA][t];
        out[Bx + (long)bB * Tx + t] = (float)path_s[sB][t];
    }
}

extern "C" void kernel_launch(void* const* d_in, const int* in_sizes, int n_in,
                              void* d_out, int out_size)
{
    const float* em     = (const float*)d_in[0];
    const int*   tags   = (const int*)d_in[1];
    const int*   mask   = (const int*)d_in[2];
    const float* trans  = (const float*)d_in[3];
    const float* startt = (const float*)d_in[4];
    const float* endt   = (const float*)d_in[5];
    float* out = (float*)d_out;

    crf_forward<<<GRID, WPB * 32>>>(em, mask, trans, startt, endt, out);
    crf_backtrace<<<Bx / (2 * BTW), BTW * 32>>>(em, tags, mask, trans, startt, endt, out);
}

// round 12
// speedup vs baseline: 1.5704x; 1.0894x over previous
#include <cuda_runtime.h>
#include <cuda_bf16.h>
#include <cstdint>

#define Bx 1024
#define Tx 512
#define Kx 64
#define WPB 7
#define GRID ((Bx + WPB - 1) / WPB)   // 147

// v rows: g_v[(b*511 + t)*32 + l] = (v_t[l], v_t[l+32]), t = 0..510
__device__ float2 g_v[(long)Bx * 511 * 32];
__device__ int g_last[Bx];

#define NEG_INF __int_as_float(0xff800000)

// Block: 14 warps. Warp w in [0,7): logZ for batch base+w.
//                  Warp w in [7,14): Viterbi for batch base+(w-7).
__global__ __launch_bounds__(14 * 32, 1) void crf_forward(
    const float* __restrict__ em, const int* __restrict__ mask,
    const float* __restrict__ trans, const float* __restrict__ startt,
    const float* __restrict__ endt, float* __restrict__ out)
{
    __shared__ float2 Tsm[32 * 32];          // T rows i in [32,64): (T[i][l], T[i][l+32])
    __shared__ unsigned int Esm[32 * 32];    // E rows i in [32,64): bf16x2
    __shared__ __align__(8) float Ssm[WPB][Kx];   // logZ exchange
    __shared__ __align__(8) float Vsm[WPB][Kx];   // viterbi exchange
    __shared__ unsigned char maskb[WPB][Tx];

    const int tid = threadIdx.x;
    const int wid = tid >> 5;
    const int l = tid & 31;
    const int grp = (wid < WPB) ? wid : (wid - WPB);
    const bool is_logz = (wid < WPB);
    const int b = blockIdx.x * WPB + grp;
    const bool active = (b < Bx);

    // block-wide init of shared tables
    for (int idx = tid; idx < 32 * 32; idx += 14 * 32) {
        int i = (idx >> 5) + 32, c = idx & 31;
        float t0 = trans[i * Kx + c];
        float t1 = trans[i * Kx + c + 32];
        Tsm[idx] = make_float2(t0, t1);
        __nv_bfloat162 h = __float22bfloat162_rn(make_float2(__expf(t0), __expf(t1)));
        Esm[idx] = *reinterpret_cast<unsigned int*>(&h);
    }
    if (is_logz && active) {
        for (int t = l; t < Tx; t += 32)
            maskb[grp][t] = (unsigned char)(mask[b * Tx + t] != 0);
    }
    __syncthreads();
    if (!active) return;

    const float* emp = em + (long)b * Tx * Kx;

    if (is_logz) {
        // ---------------- logZ warp: linear-domain s-recurrence ----------------
        unsigned int ee[32];                 // E rows i in [0,32) as bf16x2
        #pragma unroll
        for (int i = 0; i < 32; ++i) {
            float t0 = trans[i * Kx + l];
            float t1 = trans[i * Kx + l + 32];
            __nv_bfloat162 h = __float22bfloat162_rn(
                make_float2(__expf(t0), __expf(t1)));
            ee[i] = *reinterpret_cast<unsigned int*>(&h);
        }

        float s0 = __expf(startt[l] + emp[l]);
        float s1 = __expf(startt[l + 32] + emp[l + 32]);
        float L = 0.f;

        for (int t = 1; t < Tx; ++t) {
            const float e0 = __ldg(emp + t * Kx + l);
            const float e1 = __ldg(emp + t * Kx + l + 32);
            const float eem0 = __expf(e0);
            const float eem1 = __expf(e1);
            const int mt = maskb[grp][t];

            Ssm[grp][l] = s0;
            Ssm[grp][l + 32] = s1;
            __syncwarp();

            float acc0A = 0.f, acc0B = 0.f, acc1A = 0.f, acc1B = 0.f;
            #pragma unroll
            for (int ii = 0; ii < 16; ++ii) {
                const float2 sp = *(const float2*)(&Ssm[grp][2 * ii]);
                {
                    unsigned int ep = ee[2 * ii];
                    acc0A += sp.x * __uint_as_float(ep << 16);
                    acc1A += sp.x * __uint_as_float(ep & 0xffff0000u);
                }
                {
                    unsigned int ep = ee[2 * ii + 1];
                    acc0B += sp.y * __uint_as_float(ep << 16);
                    acc1B += sp.y * __uint_as_float(ep & 0xffff0000u);
                }
            }
            #pragma unroll
            for (int ii = 0; ii < 16; ++ii) {
                const float2 sp = *(const float2*)(&Ssm[grp][32 + 2 * ii]);
                {
                    unsigned int ep = Esm[(2 * ii) * 32 + l];
                    acc0A += sp.x * __uint_as_float(ep << 16);
                    acc1A += sp.x * __uint_as_float(ep & 0xffff0000u);
                }
                {
                    unsigned int ep = Esm[(2 * ii + 1) * 32 + l];
                    acc0B += sp.y * __uint_as_float(ep << 16);
                    acc1B += sp.y * __uint_as_float(ep & 0xffff0000u);
                }
            }

            const float ns0 = (acc0A + acc0B) * eem0;
            const float ns1 = (acc1A + acc1B) * eem1;
            if (mt) { s0 = ns0; s1 = ns1; }

            if ((t & 3) == 0) {
                float c = __shfl_sync(0xffffffffu, s0, 0);
                float r = __fdividef(1.0f, c);
                s0 *= r; s1 *= r;
                L += __logf(c);
            }
            __syncwarp();
        }

        const float x0 = L + __logf(s0) + endt[l];
        const float x1 = L + __logf(s1) + endt[l + 32];
        float mm = fmaxf(x0, x1);
        #pragma unroll
        for (int o = 16; o; o >>= 1)
            mm = fmaxf(mm, __shfl_xor_sync(0xffffffffu, mm, o));
        float s = __expf(x0 - mm) + __expf(x1 - mm);
        #pragma unroll
        for (int o = 16; o; o >>= 1)
            s += __shfl_xor_sync(0xffffffffu, s, o);
        if (l == 0) out[b] = mm + __logf(s);
    } else {
        // ---------------- Viterbi warp: max-plus v-recurrence (bit-exact) ----------------
        float tr0[32], tr1[32];              // T rows i in [0,32)
        #pragma unroll
        for (int i = 0; i < 32; ++i) {
            tr0[i] = __ldg(trans + i * Kx + l);
            tr1[i] = __ldg(trans + i * Kx + l + 32);
        }

        float2* vout = g_v + (long)b * 511 * 32 + l;
        float v0 = startt[l] + emp[l];
        float v1 = startt[l + 32] + emp[l + 32];
        vout[0] = make_float2(v0, v1);

        for (int t = 1; t < Tx; ++t) {
            const float e0 = __ldg(emp + t * Kx + l);
            const float e1 = __ldg(emp + t * Kx + l + 32);
            const int mt = maskb[grp][t];

            Vsm[grp][l] = v0;
            Vsm[grp][l + 32] = v1;
            __syncwarp();

            float b0A = NEG_INF, b0B = NEG_INF, b1A = NEG_INF, b1B = NEG_INF;
            #pragma unroll
            for (int ii = 0; ii < 16; ++ii) {
                const float2 vp = *(const float2*)(&Vsm[grp][2 * ii]);
                b0A = fmaxf(b0A, vp.x + tr0[2 * ii]);
                b1A = fmaxf(b1A, vp.x + tr1[2 * ii]);
                b0B = fmaxf(b0B, vp.y + tr0[2 * ii + 1]);
                b1B = fmaxf(b1B, vp.y + tr1[2 * ii + 1]);
            }
            #pragma unroll
            for (int ii = 0; ii < 16; ++ii) {
                const float2 vp = *(const float2*)(&Vsm[grp][32 + 2 * ii]);
                const float2 ta = Tsm[(2 * ii) * 32 + l];
                const float2 tb = Tsm[(2 * ii + 1) * 32 + l];
                b0A = fmaxf(b0A, vp.x + ta.x);
                b1A = fmaxf(b1A, vp.x + ta.y);
                b0B = fmaxf(b0B, vp.y + tb.x);
                b1B = fmaxf(b1B, vp.y + tb.y);
            }

            const float nv0 = fmaxf(b0A, b0B) + e0;
            const float nv1 = fmaxf(b1A, b1B) + e1;
            if (mt) { v0 = nv0; v1 = nv1; }

            if (t < 511) vout[t * 32] = make_float2(v0, v1);
            __syncwarp();
        }

        // last tag: argmax(v + end), first-index tie-break
        Vsm[grp][l] = v0 + endt[l];
        Vsm[grp][l + 32] = v1 + endt[l + 32];
        __syncwarp();
        if (l == 0) {
            float bb = Vsm[grp][0]; int aa = 0;
            for (int i = 1; i < Kx; ++i) {
                float x = Vsm[grp][i];
                if (x > bb) { bb = x; aa = i; }
            }
            g_last[b] = aa;
        }
    }
}

// Monotone bijective float -> u32 key (total order identical to < on finite floats)
__device__ __forceinline__ unsigned int fkey(float f) {
    unsigned int u = __float_as_uint(f);
    return (u & 0x80000000u) ? ~u : (u | 0x80000000u);
}

#define BTW 8   // warps per backtrace block; each warp handles 2 batches

__global__ __launch_bounds__(BTW * 32) void crf_backtrace(
    const float* __restrict__ em, const int* __restrict__ tags,
    const int* __restrict__ mask, const float* __restrict__ trans,
    const float* __restrict__ startt, const float* __restrict__ endt,
    float* __restrict__ out)
{
    // Tt[c][l] = (T[l][c], T[l+32][c])  — transposed, paired
    __shared__ float2 Tt[Kx][32];
    __shared__ unsigned char path_s[2 * BTW][Tx];
    __shared__ unsigned char mk[2 * BTW][Tx];

    const int tid = threadIdx.x;
    const int w = tid >> 5;
    const int l = tid & 31;
    const int bA = blockIdx.x * (2 * BTW) + 2 * w;
    const int bB = bA + 1;
    const int sA = 2 * w, sB = 2 * w + 1;

    for (int idx = tid; idx < Kx * 32; idx += BTW * 32) {
        int c = idx >> 5, r = idx & 31;
        Tt[c][r] = make_float2(trans[r * Kx + c], trans[(r + 32) * Kx + c]);
    }
    for (int t = l; t < Tx; t += 32) {
        mk[sA][t] = (unsigned char)(mask[bA * Tx + t] != 0);
        mk[sB][t] = (unsigned char)(mask[bB * Tx + t] != 0);
    }
    __syncthreads();

    // ---- gold score for both batches (warp-parallel) ----
    #pragma unroll
    for (int p = 0; p < 2; ++p) {
        const int b = (p == 0) ? bA : bB;
        const int sl = (p == 0) ? sA : sB;
        float gp = 0.f; int cnt = 0;
        for (int t = l; t < Tx; t += 32) {
            int mkt = mk[sl][t];
            float mf = (float)mkt;
            cnt += mkt;
            int tg = tags[b * Tx + t];
            gp += em[((long)b * Tx + t) * Kx + tg] * mf;
            if (t > 0)
                gp += trans[tags[b * Tx + t - 1] * Kx + tg] * mf;
        }
        #pragma unroll
        for (int o = 16; o; o >>= 1) {
            gp  += __shfl_xor_sync(0xffffffffu, gp, o);
            cnt += __shfl_xor_sync(0xffffffffu, cnt, o);
        }
        if (l == 0) {
            int tg0 = tags[b * Tx];
            int tgl = tags[b * Tx + cnt - 1];
            out[b] = out[b] - (gp + startt[tg0] + endt[tgl]);  // nll
        }
    }

    // ---- dual-chain path recovery: two independent batches interleaved ----
    const float2* vrA = g_v + (long)bA * 511 * 32 + l;
    const float2* vrB = g_v + (long)bB * 511 * 32 + l;
    int curA = g_last[bA];
    int curB = g_last[bB];
    path_s[sA][Tx - 1] = (unsigned char)curA;
    path_s[sB][Tx - 1] = (unsigned char)curB;

    float2 ringA[8], ringB[8];
    #pragma unroll
    for (int k = 0; k < 8; ++k) {
        ringA[k] = __ldg(vrA + (510 - k) * 32);
        ringB[k] = __ldg(vrB + (510 - k) * 32);
    }

    #define BT_STEP2(S, VA, VB)                                              \
    {                                                                        \
        const int t_ = 511 - (S);                                            \
        float2 tpA = Tt[curA][l];                                            \
        float2 tpB = Tt[curB][l];                                            \
        unsigned int kA0 = fkey((VA).x + tpA.x);                             \
        unsigned int kA1 = fkey((VA).y + tpA.y);                             \
        unsigned int kB0 = fkey((VB).x + tpB.x);                             \
        unsigned int kB1 = fkey((VB).y + tpB.y);                             \
        unsigned int kmA = __reduce_max_sync(0xffffffffu,                    \
                                             kA0 > kA1 ? kA0 : kA1);         \
        unsigned int kmB = __reduce_max_sync(0xffffffffu,                    \
                                             kB0 > kB1 ? kB0 : kB1);         \
        unsigned int mA0 = __ballot_sync(0xffffffffu, kA0 == kmA);           \
        unsigned int mA1 = __ballot_sync(0xffffffffu, kA1 == kmA);           \
        unsigned int mB0 = __ballot_sync(0xffffffffu, kB0 == kmB);           \
        unsigned int mB1 = __ballot_sync(0xffffffffu, kB1 == kmB);           \
        int ncA = mA0 ? (__ffs(mA0) - 1) : (32 + __ffs(mA1) - 1);            \
        int ncB = mB0 ? (__ffs(mB0) - 1) : (32 + __ffs(mB1) - 1);            \
        curA = mk[sA][t_] ? ncA : curA;                                      \
        curB = mk[sB][t_] ? ncB : curB;                                      \
        path_s[sA][t_ - 1] = (unsigned char)curA;                            \
        path_s[sB][t_ - 1] = (unsigned char)curB;                            \
    }

    for (int s0 = 0; s0 < 504; s0 += 8) {
        #pragma unroll
        for (int k = 0; k < 8; ++k) {
            const int s = s0 + k;
            const float2 vA = ringA[k];
            const float2 vB = ringB[k];
            const int rp = 510 - (s + 8);           // row for step s+8
            const int rpc = (rp >= 0 ? rp : 0) * 32;
            ringA[k] = __ldg(vrA + rpc);
            ringB[k] = __ldg(vrB + rpc);
            BT_STEP2(s, vA, vB);
        }
    }
    #pragma unroll
    for (int k = 0; k < 7; ++k) {
        const int s = 504 + k;
        const float2 vA = ringA[k];
        const float2 vB = ringB[k];
        BT_STEP2(s, vA, vB);
    }
    #undef BT_STEP2

    __syncwarp();
    for (int t = l; t < Tx; t += 32) {
        out[Bx + (long)bA * Tx + t] = (float)path_s[sA][t];
        out[Bx + (long)bB * Tx + t] = (float)path_s[sB][t];
    }
}

extern "C" void kernel_launch(void* const* d_in, const int* in_sizes, int n_in,
                              void* d_out, int out_size)
{
    const float* em     = (const float*)d_in[0];
    const int*   tags   = (const int*)d_in[1];
    const int*   mask   = (const int*)d_in[2];
    const float* trans  = (const float*)d_in[3];
    const float* startt = (const float*)d_in[4];
    const float* endt   = (const float*)d_in[5];
    float* out = (float*)d_out;

    crf_forward<<<GRID, 14 * 32>>>(em, mask, trans, startt, endt, out);
    crf_backtrace<<<Bx / (2 * BTW), BTW * 32>>>(em, tags, mask, trans, startt, endt, out);
}